// round 8
// baseline (speedup 1.0000x reference)
#include <cuda_runtime.h>

#define KC 32
#define LC 64
#define HC 256
#define OC 32
#define BMAX 256
#define NMAX 100000
#define CPG 4

#define ZW1_SMEM ((LC*HC + 4*LC) * 4)
#define MAIN_SMEM ((KC*HC + HC*OC + 64*KC + 8*8*HC + HC + OC) * 4 + 64 * 4)

// ---------------- device scratch (no allocations allowed) ----------------
__device__ float g_zw1[BMAX * KC * HC];   // 8 MB: z @ W1 per (graph, cluster)
__device__ int   g_perm[NMAX];            // node ids sorted by graph
__device__ int   g_hist[BMAX];
__device__ int   g_binstart[BMAX];
__device__ int   g_cursor[BMAX];

// ---------------- 0. zero histogram (graph replays must be idempotent) ----
__global__ void init_kernel() {
    int t = threadIdx.x;
    if (t < BMAX) g_hist[t] = 0;
}

// ---------------- 1. zW1[b,k,:] = z[b,k,:] @ W1  (B*K rows) ---------------
__global__ void zw1_kernel(const float* __restrict__ z,
                           const float* __restrict__ W1) {
    extern __shared__ __align__(16) float sm[];
    float* w1s = sm;              // LC*HC floats (64 KB)
    float* zs  = sm + LC * HC;    // 4*LC floats
    int tid = threadIdx.x;        // 256 threads

    for (int i = tid; i < (LC * HC) / 4; i += 256)
        ((float4*)w1s)[i] = ((const float4*)W1)[i];

    int row0 = blockIdx.x * 16;   // 16 rows per CTA, in groups of 4
    for (int g = 0; g < 4; g++) {
        int rbase = row0 + g * 4;
        __syncthreads();
        int rr = tid >> 6, ll = tid & 63;
        zs[rr * LC + ll] = z[(size_t)(rbase + rr) * LC + ll];
        __syncthreads();

        float a0 = 0.f, a1 = 0.f, a2 = 0.f, a3 = 0.f;
        #pragma unroll
        for (int l = 0; l < LC; l++) {
            float w = w1s[l * HC + tid];     // bank = tid%32, conflict-free
            a0 += zs[0 * LC + l] * w;
            a1 += zs[1 * LC + l] * w;
            a2 += zs[2 * LC + l] * w;
            a3 += zs[3 * LC + l] * w;
        }
        g_zw1[(size_t)(rbase + 0) * HC + tid] = a0;
        g_zw1[(size_t)(rbase + 1) * HC + tid] = a1;
        g_zw1[(size_t)(rbase + 2) * HC + tid] = a2;
        g_zw1[(size_t)(rbase + 3) * HC + tid] = a3;
    }
}

// ---------------- 2. histogram of batch ids (batch is INT32: JAX x64 off) -
__global__ void hist_kernel(const int* __restrict__ batch, int n, int B) {
    __shared__ int sh[BMAX];
    int tid = threadIdx.x;
    sh[tid] = 0;
    __syncthreads();
    for (int i = blockIdx.x * blockDim.x + tid; i < n; i += gridDim.x * blockDim.x) {
        int b = batch[i];
        if (b >= 0 && b < B) atomicAdd(&sh[b], 1);
    }
    __syncthreads();
    if (sh[tid]) atomicAdd(&g_hist[tid], sh[tid]);
}

// ---------------- 3. exclusive scan (parallel — serial would cost 40us) ---
__global__ void scan_kernel() {
    __shared__ int tmp[BMAX];
    int tid = threadIdx.x;
    int v0 = g_hist[tid];
    tmp[tid] = v0;
    __syncthreads();
    for (int d = 1; d < BMAX; d <<= 1) {
        int v = (tid >= d) ? tmp[tid - d] : 0;
        __syncthreads();
        tmp[tid] += v;
        __syncthreads();
    }
    int start = tmp[tid] - v0;     // exclusive
    g_binstart[tid] = start;
    g_cursor[tid]   = start;
}

// ---------------- 4. scatter node ids into bins ---------------------------
__global__ void scatter_kernel(const int* __restrict__ batch, int n, int B) {
    for (int i = blockIdx.x * blockDim.x + threadIdx.x; i < n;
         i += gridDim.x * blockDim.x) {
        int b = batch[i];
        if (b < 0 || b >= B) continue;
        int pos = atomicAdd(&g_cursor[b], 1);
        if (pos < NMAX) g_perm[pos] = i;
    }
}

// ---------------- 5. main fused kernel ------------------------------------
// CTA = (graph b, chunk stride CPG). SMEM: zW1[b] (32KB) + W2 (32KB) resident.
// Each warp: 8-node register tile; h-stage 64 accumulators/lane,
// out-stage via per-warp SMEM h staging with W2 registered outer loop.
__global__ __launch_bounds__(256, 1)
void main_kernel(const float* __restrict__ s, const float* __restrict__ W2,
                 const float* __restrict__ b1, const float* __restrict__ b2,
                 float* __restrict__ out, int B) {
    extern __shared__ __align__(16) float sm[];
    float* zw1s = sm;                    // KC*HC   = 8192
    float* w2s  = zw1s + KC * HC;        // HC*OC   = 8192  (layout [j][o])
    float* ss   = w2s + HC * OC;         // 64*KC   = 2048
    float* hsm  = ss + 64 * KC;          // 8*8*HC  = 16384
    float* b1s  = hsm + 8 * 8 * HC;      // 256
    float* b2s  = b1s + HC;              // 32
    int*   nids = (int*)(b2s + OC);      // 64

    int tid = threadIdx.x;
    int b   = blockIdx.x % B;
    int c0  = blockIdx.x / B;
    int cnt = g_hist[b];
    if (c0 * 64 >= cnt) return;          // nothing for this CTA
    int start = g_binstart[b];

    // prologue: stage per-graph zW1 and shared weights
    const float4* zw1g = (const float4*)(g_zw1 + (size_t)b * KC * HC);
    #pragma unroll
    for (int i = 0; i < 8; i++)
        ((float4*)zw1s)[tid + i * 256] = zw1g[tid + i * 256];
    #pragma unroll
    for (int i = 0; i < 8; i++)
        ((float4*)w2s)[tid + i * 256] = ((const float4*)W2)[tid + i * 256];
    b1s[tid] = b1[tid];
    if (tid < OC) b2s[tid] = b2[tid];

    int w = tid >> 5, lane = tid & 31;
    float* hw = hsm + w * 8 * HC;        // this warp's h staging

    for (int c = c0; c * 64 < cnt; c += CPG) {
        int nbase = c * 64;
        __syncthreads();                 // covers prologue + ss/nids reuse
        if (tid < 64) {
            int idx = nbase + tid;
            nids[tid] = (idx < cnt) ? g_perm[start + idx] : -1;
        }
        __syncthreads();
        // stage s rows for the 64 nodes (zero-fill invalid tail)
        for (int idx = tid; idx < 64 * 8; idx += 256) {
            int i = idx >> 3, q = idx & 7;
            int nid = nids[i];
            float4 v = make_float4(0.f, 0.f, 0.f, 0.f);
            if (nid >= 0) v = ((const float4*)(s + (size_t)nid * KC))[q];
            ((float4*)(ss + i * KC))[q] = v;
        }
        __syncthreads();

        // ---- h-stage: h[t][j] = b1[j] + sum_k s[t,k]*zW1[b,k,j], j=lane*8+r
        float ha[8][8];
        float4 bva = *(float4*)&b1s[lane * 8];
        float4 bvb = *(float4*)&b1s[lane * 8 + 4];
        #pragma unroll
        for (int t = 0; t < 8; t++) {
            ha[t][0] = bva.x; ha[t][1] = bva.y; ha[t][2] = bva.z; ha[t][3] = bva.w;
            ha[t][4] = bvb.x; ha[t][5] = bvb.y; ha[t][6] = bvb.z; ha[t][7] = bvb.w;
        }
        const float* ssw = ss + w * 8 * KC;
        #pragma unroll 4
        for (int k = 0; k < KC; k++) {
            float4 wa = *(float4*)&zw1s[k * HC + lane * 8];
            float4 wb = *(float4*)&zw1s[k * HC + lane * 8 + 4];
            #pragma unroll
            for (int t = 0; t < 8; t++) {
                float sv = ssw[t * KC + k];           // warp broadcast
                ha[t][0] += sv * wa.x; ha[t][1] += sv * wa.y;
                ha[t][2] += sv * wa.z; ha[t][3] += sv * wa.w;
                ha[t][4] += sv * wb.x; ha[t][5] += sv * wb.y;
                ha[t][6] += sv * wb.z; ha[t][7] += sv * wb.w;
            }
        }
        // relu + stage h to SMEM (warp-local)
        #pragma unroll
        for (int t = 0; t < 8; t++) {
            float4 v0, v1;
            v0.x = fmaxf(ha[t][0], 0.f); v0.y = fmaxf(ha[t][1], 0.f);
            v0.z = fmaxf(ha[t][2], 0.f); v0.w = fmaxf(ha[t][3], 0.f);
            v1.x = fmaxf(ha[t][4], 0.f); v1.y = fmaxf(ha[t][5], 0.f);
            v1.z = fmaxf(ha[t][6], 0.f); v1.w = fmaxf(ha[t][7], 0.f);
            *(float4*)&hw[t * HC + lane * 8]     = v0;
            *(float4*)&hw[t * HC + lane * 8 + 4] = v1;
        }
        __syncwarp();

        // ---- out-stage: out[t][o=lane] = b2[o] + sum_j h[t][j]*W2[j][o]
        float acc[8];
        #pragma unroll
        for (int t = 0; t < 8; t++) acc[t] = b2s[lane];
        #pragma unroll 4
        for (int j4 = 0; j4 < HC / 4; j4++) {
            int j = j4 * 4;
            float u0 = w2s[(j + 0) * OC + lane];      // conflict-free
            float u1 = w2s[(j + 1) * OC + lane];
            float u2 = w2s[(j + 2) * OC + lane];
            float u3 = w2s[(j + 3) * OC + lane];
            #pragma unroll
            for (int t = 0; t < 8; t++) {
                float4 hv = *(float4*)&hw[t * HC + j];  // warp broadcast
                acc[t] += hv.x * u0 + hv.y * u1 + hv.z * u2 + hv.w * u3;
            }
        }
        #pragma unroll
        for (int t = 0; t < 8; t++) {
            int nid = nids[w * 8 + t];
            if (nid >= 0) out[(size_t)nid * OC + lane] = acc[t];  // coalesced row
        }
        __syncwarp();   // hw safe to rewrite next chunk
    }
}

// ---------------- launch ---------------------------------------------------
extern "C" void kernel_launch(void* const* d_in, const int* in_sizes, int n_in,
                              void* d_out, int out_size) {
    const float* z     = (const float*)d_in[0];
    const float* s     = (const float*)d_in[1];
    const int*   batch = (const int*)d_in[2];   // JAX x64 disabled -> int32
    const float* W1    = (const float*)d_in[3];
    const float* b1    = (const float*)d_in[4];
    const float* W2    = (const float*)d_in[5];
    const float* b2    = (const float*)d_in[6];
    float*       out   = (float*)d_out;

    int n = in_sizes[2];                 // N nodes (batch element count)
    int B = in_sizes[0] / (KC * LC);     // graphs

    cudaFuncSetAttribute(zw1_kernel,
        cudaFuncAttributeMaxDynamicSharedMemorySize, ZW1_SMEM);
    cudaFuncSetAttribute(main_kernel,
        cudaFuncAttributeMaxDynamicSharedMemorySize, MAIN_SMEM);

    init_kernel<<<1, 256>>>();
    zw1_kernel<<<(B * KC) / 16, 256, ZW1_SMEM>>>(z, W1);
    hist_kernel<<<128, 256>>>(batch, n, B);
    scan_kernel<<<1, BMAX>>>();
    scatter_kernel<<<256, 256>>>(batch, n, B);
    main_kernel<<<B * CPG, 256, MAIN_SMEM>>>(s, W2, b1, b2, out, B);
}